// round 17
// baseline (speedup 1.0000x reference)
#include <cuda_runtime.h>
#include <cuda_fp16.h>
#include <math_constants.h>
#include <cstdint>

#define N_NODES 100000
#define E_EDGES 1600000
#define IN_F    256
#define OUT_F   128
#define ALPHA   0.2f

// ---------------- scratch (static device globals; no allocation) ------------
__device__ __half g_Whh[(size_t)N_NODES * OUT_F];   // 25.6 MB (fp16 Wh)
__device__ float  g_f1[N_NODES];
__device__ float  g_f2[N_NODES];
__device__ float  g_att[E_EDGES];                   // logits (fallback path only)
__device__ int    g_row_ptr[N_NODES + 1];
__device__ __align__(16) uint8_t g_Bblk[65536];     // blocked fp16 W

// ---------------- warp-mma helpers (plain sm_103-safe PTX) ------------------
__device__ __forceinline__ uint32_t smem_u32(const void* p) {
    uint32_t a;
    asm("{ .reg .u64 t; cvta.to.shared.u64 t, %1; cvt.u32.u64 %0, t; }"
        : "=r"(a) : "l"(p));
    return a;
}
__device__ __forceinline__ void ldsm_x4(uint32_t* r, uint32_t addr) {
    asm volatile("ldmatrix.sync.aligned.m8n8.x4.shared.b16 {%0,%1,%2,%3}, [%4];"
                 : "=r"(r[0]), "=r"(r[1]), "=r"(r[2]), "=r"(r[3]) : "r"(addr));
}
__device__ __forceinline__ void ldsm_x4_t(uint32_t* r, uint32_t addr) {
    asm volatile("ldmatrix.sync.aligned.m8n8.x4.trans.shared.b16 {%0,%1,%2,%3}, [%4];"
                 : "=r"(r[0]), "=r"(r[1]), "=r"(r[2]), "=r"(r[3]) : "r"(addr));
}
__device__ __forceinline__ void mma_f16(float (&d)[4], const uint32_t* a,
                                        const uint32_t* b) {
    asm("mma.sync.aligned.m16n8k16.row.col.f32.f16.f16.f32 "
        "{%0,%1,%2,%3}, {%4,%5,%6,%7}, {%8,%9}, {%0,%1,%2,%3};"
        : "+f"(d[0]), "+f"(d[1]), "+f"(d[2]), "+f"(d[3])
        : "r"(a[0]), "r"(a[1]), "r"(a[2]), "r"(a[3]), "r"(b[0]), "r"(b[1]));
}

// ---------------- K0: merged prep (W convert + CSR row_ptr) -----------------
// blocks [0,32): convert W -> blocked fp16
// blocks [32,...): build row_ptr from sorted row (4 edges/thread)
__global__ void prep_kernel(const float* __restrict__ Wp,
                            const int* __restrict__ row, int E, int N) {
    if (blockIdx.x < 32) {
        int idx4 = blockIdx.x * 256 + threadIdx.x;   // 0..8191
        int k = idx4 >> 5;
        int n = (idx4 & 31) << 2;
        float4 v = *(const float4*)(Wp + (size_t)k * OUT_F + n);
        __half2 h0 = __floats2half2_rn(v.x, v.y);
        __half2 h1 = __floats2half2_rn(v.z, v.w);
        uint32_t off = (uint32_t)((k >> 4) * 16 + (n >> 3)) * 256
                     + ((k >> 3) & 1) * 128 + (k & 7) * 16 + (n & 7) * 2;
        uint2 uh;
        uh.x = *(uint32_t*)&h0; uh.y = *(uint32_t*)&h1;
        *(uint2*)(g_Bblk + off) = uh;
        return;
    }
    int t = (blockIdx.x - 32) * blockDim.x + threadIdx.x;
    int i0 = t * 4;
    if (i0 >= E) return;
    int prev = (i0 == 0) ? -1 : __ldg(row + i0 - 1);
    if (i0 + 3 < E) {
        int4 r4 = *(const int4*)(row + i0);
        int rr[4] = {r4.x, r4.y, r4.z, r4.w};
        #pragma unroll
        for (int u = 0; u < 4; ++u) {
            int r = rr[u];
            if (r != prev)
                for (int q = prev + 1; q <= r; ++q) g_row_ptr[q] = i0 + u;
            prev = r;
        }
        if (i0 + 4 >= E)
            for (int q = prev + 1; q <= N; ++q) g_row_ptr[q] = E;
    } else {
        for (int u = 0; u < 4 && i0 + u < E; ++u) {
            int r = __ldg(row + i0 + u);
            if (r != prev)
                for (int q = prev + 1; q <= r; ++q) g_row_ptr[q] = i0 + u;
            prev = r;
        }
        for (int q = prev + 1; q <= N; ++q) g_row_ptr[q] = E;
    }
}

// ---------------- K1: persistent pipelined fp16 warp-MMA GEMM ---------------
// SMEM: B [0,64K); A buf0 [64K,128K); A buf1 [128K,192K); scores [192K,+2K)
#define SM_B    0
#define SM_A0   65536
#define SM_SC   196608
#define SM_TOTAL 198656

__device__ __forceinline__ uint32_t a_blk_off(int arow, int kq) {
    return (uint32_t)(((arow >> 4) * 16 + (kq >> 4)) << 9)
         + ((arow >> 3) & 1) * 128 + ((kq >> 3) & 1) * 256
         + (arow & 7) * 16 + (kq & 7) * 2;
}

__global__ __launch_bounds__(256, 1)
void gemm_tc_kernel(const float* __restrict__ A,
                    const float* __restrict__ a_src,
                    const float* __restrict__ a_dest, int M, int ntiles) {
    extern __shared__ char smem[];
    uint32_t sb = smem_u32(smem);
    const int tid  = threadIdx.x;
    const int wid  = tid >> 5;
    const int lane = tid & 31;
    const int mw   = wid >> 1;     // 0..3 (M dir)
    const int nw   = wid & 1;      // 0..1 (N dir)

    // ---- load pre-blocked B once per CTA ----
    #pragma unroll
    for (int i = 0; i < 16; ++i)
        *(uint4*)(smem + i * 4096 + tid * 16) =
            *(const uint4*)(g_Bblk + i * 4096 + tid * 16);

    const int arow = tid >> 1;            // 0..127
    const int c0   = (tid & 1) * 128;     // k base: thread covers 128 k's

    // ---- convert first tile into buf 0 ----
    int tile = blockIdx.x;
    if (tile < ntiles) {
        const int m0g = tile * 128;
        const bool av = (m0g + arow) < M;
        const float* aptr = A + (size_t)(m0g + arow) * IN_F + c0;
        #pragma unroll 8
        for (int i = 0; i < 32; ++i) {
            float4 v = av ? ((const float4*)aptr)[i]
                          : make_float4(0.f, 0.f, 0.f, 0.f);
            __half2 h0 = __floats2half2_rn(v.x, v.y);
            __half2 h1 = __floats2half2_rn(v.z, v.w);
            uint2 uh;
            uh.x = *(uint32_t*)&h0; uh.y = *(uint32_t*)&h1;
            *(uint2*)(smem + SM_A0 + a_blk_off(arow, c0 + i * 4)) = uh;
        }
    }
    __syncthreads();

    int cur = 0;
    for (; tile < ntiles; tile += gridDim.x) {
        const int m0g = tile * 128;
        const int nt_ = tile + gridDim.x;
        const bool hasnext = nt_ < ntiles;
        const bool nav = hasnext && (nt_ * 128 + arow) < M;
        const float* naptr = A + (size_t)(nt_ * 128 + arow) * IN_F + c0;

        float acc[16][4];
        #pragma unroll
        for (int t = 0; t < 16; ++t)
            #pragma unroll
            for (int q = 0; q < 4; ++q) acc[t][q] = 0.f;

        const uint32_t abase = sb + SM_A0 + (uint32_t)cur * 65536;
        char* nbuf = smem + SM_A0 + (uint32_t)(1 - cur) * 65536;

        #pragma unroll
        for (int q = 0; q < 4; ++q) {
            float4 pf[8];
            if (hasnext) {
                #pragma unroll
                for (int j = 0; j < 8; ++j)
                    pf[j] = nav ? ((const float4*)naptr)[q * 8 + j]
                                : make_float4(0.f, 0.f, 0.f, 0.f);
            }
            #pragma unroll
            for (int kb2 = 0; kb2 < 4; ++kb2) {
                const int kb = q * 4 + kb2;
                uint32_t ah0[4], ah1[4];
                uint32_t at0 = abase + ((uint32_t)((mw * 2 + 0) * 16 + kb) << 9)
                             + (lane << 4);
                uint32_t at1 = abase + ((uint32_t)((mw * 2 + 1) * 16 + kb) << 9)
                             + (lane << 4);
                ldsm_x4(ah0, at0);
                ldsm_x4(ah1, at1);
                #pragma unroll
                for (int p = 0; p < 4; ++p) {
                    int nb = nw * 8 + p * 2;
                    uint32_t bbase = sb + SM_B + ((uint32_t)(kb * 16 + nb) << 8)
                                   + (lane << 4);
                    uint32_t bh[4];
                    ldsm_x4_t(bh, bbase);
                    mma_f16(acc[2 * p],         ah0, bh + 0);
                    mma_f16(acc[8 + 2 * p],     ah1, bh + 0);
                    mma_f16(acc[2 * p + 1],     ah0, bh + 2);
                    mma_f16(acc[8 + 2 * p + 1], ah1, bh + 2);
                }
            }
            if (hasnext) {
                #pragma unroll
                for (int j = 0; j < 8; ++j) {
                    int kq = c0 + q * 32 + j * 4;
                    float4 v = pf[j];
                    __half2 h0 = __floats2half2_rn(v.x, v.y);
                    __half2 h1 = __floats2half2_rn(v.z, v.w);
                    uint2 uh;
                    uh.x = *(uint32_t*)&h0; uh.y = *(uint32_t*)&h1;
                    *(uint2*)(nbuf + a_blk_off(arow, kq)) = uh;
                }
            }
        }

        // ---- epilogue: fp16 Wh + fused f1/f2 scores (dedicated smem) -------
        float* s1p = (float*)(smem + SM_SC);           // [2][128]
        float* s2p = (float*)(smem + SM_SC + 1024);    // [2][128]
        const int qr = lane >> 2, qc = lane & 3;

        #pragma unroll
        for (int mt = 0; mt < 2; ++mt) {
            int r0 = mw * 32 + mt * 16 + qr;
            int r1 = r0 + 8;
            float s1a = 0.f, s1b = 0.f, s2a = 0.f, s2b = 0.f;
            #pragma unroll
            for (int nt = 0; nt < 8; ++nt) {
                float* d = acc[mt * 8 + nt];
                int n = nw * 64 + nt * 8 + qc * 2;
                if (m0g + r0 < M)
                    *(__half2*)(g_Whh + (size_t)(m0g + r0) * OUT_F + n)
                        = __floats2half2_rn(d[0], d[1]);
                if (m0g + r1 < M)
                    *(__half2*)(g_Whh + (size_t)(m0g + r1) * OUT_F + n)
                        = __floats2half2_rn(d[2], d[3]);
                float a0 = a_src[n], a1 = a_src[n + 1];
                float b0 = a_dest[n], b1 = a_dest[n + 1];
                s1a += d[0] * a0 + d[1] * a1;
                s1b += d[2] * a0 + d[3] * a1;
                s2a += d[0] * b0 + d[1] * b1;
                s2b += d[2] * b0 + d[3] * b1;
            }
            s1a += __shfl_xor_sync(~0u, s1a, 1); s1a += __shfl_xor_sync(~0u, s1a, 2);
            s1b += __shfl_xor_sync(~0u, s1b, 1); s1b += __shfl_xor_sync(~0u, s1b, 2);
            s2a += __shfl_xor_sync(~0u, s2a, 1); s2a += __shfl_xor_sync(~0u, s2a, 2);
            s2b += __shfl_xor_sync(~0u, s2b, 1); s2b += __shfl_xor_sync(~0u, s2b, 2);
            if (qc == 0) {
                s1p[nw * 128 + r0] = s1a;  s1p[nw * 128 + r1] = s1b;
                s2p[nw * 128 + r0] = s2a;  s2p[nw * 128 + r1] = s2b;
            }
        }
        __syncthreads();   // scores ready AND next-tile A buffer fully stored
        if (tid < 128) {
            int gm = m0g + tid;
            if (gm < M) {
                g_f1[gm] = s1p[tid] + s1p[128 + tid];
                g_f2[gm] = s2p[tid] + s2p[128 + tid];
            }
        }
        __syncthreads();
        cur ^= 1;
    }
}

// ---------------- K2: softmax + fp16 SpMM + ELU (one warp per node) ---------
__device__ __forceinline__ float leaky(float x) {
    return fmaxf(x, ALPHA * x);     // FMUL + FMNMX, branch-free
}

__global__ __launch_bounds__(256)
void aggregate_kernel(const int* __restrict__ col, float* __restrict__ out, int N) {
    int warp = (blockIdx.x * blockDim.x + threadIdx.x) >> 5;
    int lane = threadIdx.x & 31;
    if (warp >= N) return;

    int start = g_row_ptr[warp];
    int end   = g_row_ptr[warp + 1];
    int deg   = end - start;
    float f1 = g_f1[warp];

    float4 acc = make_float4(0.f, 0.f, 0.f, 0.f);
    float inv = 0.f;

    if (deg <= 32) {
        // fast path: one edge per lane; inactive lanes carry w=0, col=0 so the
        // gather loop needs no bounds checks at all.
        int j = start + lane;
        int cj = 0;
        float e = -3.0e38f;
        if (j < end) {
            cj = col[j];
            e = leaky(f1 + g_f2[cj]);
        }
        float m = e;
        #pragma unroll
        for (int o = 16; o; o >>= 1)
            m = fmaxf(m, __shfl_xor_sync(~0u, m, o));
        float w = (j < end) ? __expf(e - m) : 0.f;
        float dsum = w;
        #pragma unroll
        for (int o = 16; o; o >>= 1)
            dsum += __shfl_xor_sync(~0u, dsum, o);
        inv = (deg > 0 && dsum > 0.f) ? 1.f / dsum : 0.f;

        const uint2* base = (const uint2*)g_Whh + lane;
        // paired, predicate-free: overshoot lane has w=0 (row-0 gather is benign)
        for (int u = 0; u < deg; u += 2) {
            float w0 = __shfl_sync(~0u, w, u);
            int   c0 = __shfl_sync(~0u, cj, u);
            float w1 = __shfl_sync(~0u, w, u + 1);
            int   c1 = __shfl_sync(~0u, cj, u + 1);
            uint2 uv0 = base[(size_t)c0 * (OUT_F / 4)];
            uint2 uv1 = base[(size_t)c1 * (OUT_F / 4)];
            float2 p0 = __half22float2(*(__half2*)&uv0.x);
            float2 p1 = __half22float2(*(__half2*)&uv0.y);
            float2 q0 = __half22float2(*(__half2*)&uv1.x);
            float2 q1 = __half22float2(*(__half2*)&uv1.y);
            acc.x += w0 * p0.x + w1 * q0.x;
            acc.y += w0 * p0.y + w1 * q0.y;
            acc.z += w0 * p1.x + w1 * q1.x;
            acc.w += w0 * p1.y + w1 * q1.y;
        }
    } else {
        // fallback: two-pass via g_att cache (rare: deg > 32)
        float m = -3.0e38f;
        for (int j = start + lane; j < end; j += 32) {
            float e = leaky(f1 + g_f2[col[j]]);
            g_att[j] = e;
            m = fmaxf(m, e);
        }
        #pragma unroll
        for (int o = 16; o; o >>= 1)
            m = fmaxf(m, __shfl_xor_sync(~0u, m, o));

        float dsum = 0.f;
        const uint2* base = (const uint2*)g_Whh + lane;
        for (int j0 = start; j0 < end; j0 += 32) {
            int j = j0 + lane;
            float w = 0.f;
            int cj = 0;
            if (j < end) {
                w = __expf(g_att[j] - m);
                cj = col[j];
            }
            dsum += w;
            int cnt = min(32, end - j0);
            // paired, predicate-free within the chunk (overshoot lane w=0)
            for (int u = 0; u < cnt; u += 2) {
                float w0 = __shfl_sync(~0u, w, u);
                int   c0 = __shfl_sync(~0u, cj, u);
                float w1 = __shfl_sync(~0u, w, u + 1);
                int   c1 = __shfl_sync(~0u, cj, u + 1);
                uint2 uv0 = base[(size_t)c0 * (OUT_F / 4)];
                uint2 uv1 = base[(size_t)c1 * (OUT_F / 4)];
                float2 p0 = __half22float2(*(__half2*)&uv0.x);
                float2 p1 = __half22float2(*(__half2*)&uv0.y);
                float2 q0 = __half22float2(*(__half2*)&uv1.x);
                float2 q1 = __half22float2(*(__half2*)&uv1.y);
                acc.x += w0 * p0.x + w1 * q0.x;
                acc.y += w0 * p0.y + w1 * q0.y;
                acc.z += w0 * p1.x + w1 * q1.x;
                acc.w += w0 * p1.y + w1 * q1.y;
            }
        }
        #pragma unroll
        for (int o = 16; o; o >>= 1)
            dsum += __shfl_xor_sync(~0u, dsum, o);
        inv = (dsum > 0.f) ? 1.f / dsum : 0.f;
    }

    acc.x *= inv; acc.y *= inv; acc.z *= inv; acc.w *= inv;

    acc.x = acc.x > 0.f ? acc.x : (__expf(acc.x) - 1.f);
    acc.y = acc.y > 0.f ? acc.y : (__expf(acc.y) - 1.f);
    acc.z = acc.z > 0.f ? acc.z : (__expf(acc.z) - 1.f);
    acc.w = acc.w > 0.f ? acc.w : (__expf(acc.w) - 1.f);

    ((float4*)(out + (size_t)warp * OUT_F))[lane] = acc;
}

// ---------------- launch ----------------------------------------------------
extern "C" void kernel_launch(void* const* d_in, const int* in_sizes, int n_in,
                              void* d_out, int out_size) {
    const float* h      = (const float*)d_in[0];
    const float* W      = (const float*)d_in[1];
    const float* a_src  = (const float*)d_in[2];
    const float* a_dest = (const float*)d_in[3];
    const int*   row    = (const int*)d_in[4];
    const int*   col    = (const int*)d_in[5];
    float*       out    = (float*)d_out;

    const int M = in_sizes[0] / IN_F;   // 100000
    const int E = in_sizes[4];          // 1600000
    const int ntiles = (M + 127) / 128; // 782

    cudaFuncSetAttribute(gemm_tc_kernel,
                         cudaFuncAttributeMaxDynamicSharedMemorySize, SM_TOTAL);

    prep_kernel<<<32 + (E / 4 + 255) / 256, 256>>>(W, row, E, M);
    gemm_tc_kernel<<<148, 256, SM_TOTAL>>>(h, a_src, a_dest, M, ntiles);
    aggregate_kernel<<<(M + 7) / 8, 256>>>(col, out, M);
}